// round 6
// baseline (speedup 1.0000x reference)
#include <cuda_runtime.h>
#include <cuda_bf16.h>

typedef unsigned long long ull;
typedef unsigned int uint;

static constexpr int IMG   = 128;
static constexpr int NPIX  = IMG * IMG;      // 16384
static constexpr int CH    = 64;
static constexpr int NHEAD = 8;
static constexpr int HIDN  = 128;
static constexpr float LNEPS  = 1e-5f;
static constexpr float QSCALE = 0.35355339059327373f;   // 8^-0.5

// ---------------- scratch ----------------
__device__ __align__(16) float g_q[NHEAD * NPIX * 8];
__device__ __align__(16) unsigned short g_kb[NHEAD * NPIX * 8];   // bf16
__device__ __align__(16) unsigned short g_vb[NHEAD * NPIX * 8];   // bf16
__device__ __align__(16) float g_att[CH * NPIX];
__device__ __align__(16) float g_x1 [CH * NPIX];
__device__ __align__(16) float g_y  [CH * NPIX];
__device__ __align__(16) float g_h1 [HIDN * NPIX];

// ---------------- packed f32x2 helpers ----------------
#define FMA2(acc, a, b) asm("fma.rn.f32x2 %0, %1, %2, %0;" : "+l"(acc) : "l"(a), "l"(b))

__device__ __forceinline__ ull pk(float lo, float hi) {
    ull r; asm("mov.b64 %0, {%1, %2};" : "=l"(r) : "f"(lo), "f"(hi)); return r;
}
__device__ __forceinline__ float2 upk(ull v) {
    float2 r; asm("mov.b64 {%0, %1}, %2;" : "=f"(r.x), "=f"(r.y) : "l"(v)); return r;
}
__device__ __forceinline__ uint packbf(float a, float b) {
    __nv_bfloat162 h = __floats2bfloat162_rn(a, b);
    return *reinterpret_cast<uint*>(&h);
}
__device__ __forceinline__ ull b2u(uint u) {
    return pk(__uint_as_float(u << 16), __uint_as_float(u & 0xffff0000u));
}

// =================================================================
// Kernel A: LN1 -> QKV GEMM -> qLN/kLN -> store q fp32, k/v bf16
// 64-px tiles, grid 256, block 384 = 48 ot(4out) x 8 pt(8px)
// =================================================================
static constexpr int SMEM_A = (64 * 68 + 64 * 196) * 4;   // 67584

__global__ void __launch_bounds__(384, 2)
kA(const float* __restrict__ x, const float* __restrict__ n1w, const float* __restrict__ n1b,
   const float* __restrict__ qkvw, const float* __restrict__ qkvb,
   const float* __restrict__ qnw, const float* __restrict__ qnb,
   const float* __restrict__ knw, const float* __restrict__ knb)
{
    extern __shared__ float sm[];
    float* xs = sm;              // [64][68]
    float* wt = sm + 64 * 68;    // [64][196]
    float* qs = sm;              // staging [192][68] (reused after GEMM)
    const int tid = threadIdx.x;
    const int p0 = blockIdx.x * 64;

    for (int i = tid; i < 192 * 64; i += 384) {
        int o = i >> 6, c = i & 63;
        wt[c * 196 + o] = qkvw[i];
    }
    for (int i = tid; i < 64 * 64; i += 384) {
        int c = i >> 6, pp = i & 63;
        xs[c * 68 + pp] = x[c * NPIX + p0 + pp];
    }
    __syncthreads();

    // LN1: 4 threads per pixel
    if (tid < 256) {
        const int s = tid & 3, px = tid >> 2;
        float mean = 0.f;
        #pragma unroll
        for (int j = 0; j < 16; j++) mean += xs[(s * 16 + j) * 68 + px];
        mean += __shfl_xor_sync(0xffffffffu, mean, 1);
        mean += __shfl_xor_sync(0xffffffffu, mean, 2);
        mean *= (1.f / 64);
        float var = 0.f;
        #pragma unroll
        for (int j = 0; j < 16; j++) { float d = xs[(s * 16 + j) * 68 + px] - mean; var += d * d; }
        var += __shfl_xor_sync(0xffffffffu, var, 1);
        var += __shfl_xor_sync(0xffffffffu, var, 2);
        float inv = rsqrtf(var * (1.f / 64) + LNEPS);
        #pragma unroll
        for (int j = 0; j < 16; j++) {
            int c = s * 16 + j;
            xs[c * 68 + px] = (xs[c * 68 + px] - mean) * inv * n1w[c] + n1b[c];
        }
    }
    __syncthreads();

    // GEMM: 4 out x 8 px per thread
    const int ot = tid >> 3;        // 0..47
    const int pt = tid & 7;         // 0..7
    ull acc2[4][4];
    #pragma unroll
    for (int oi = 0; oi < 4; oi++)
        #pragma unroll
        for (int pj = 0; pj < 4; pj++) acc2[oi][pj] = 0ull;

    #pragma unroll 2
    for (int c = 0; c < 64; c++) {
        float4 w = *reinterpret_cast<const float4*>(&wt[c * 196 + ot * 4]);
        ulonglong2 a0 = *reinterpret_cast<const ulonglong2*>(&xs[c * 68 + pt * 8]);
        ulonglong2 a1 = *reinterpret_cast<const ulonglong2*>(&xs[c * 68 + pt * 8 + 4]);
        float wf[4] = {w.x, w.y, w.z, w.w};
        #pragma unroll
        for (int oi = 0; oi < 4; oi++) {
            ull wp = pk(wf[oi], wf[oi]);
            FMA2(acc2[oi][0], wp, a0.x);
            FMA2(acc2[oi][1], wp, a0.y);
            FMA2(acc2[oi][2], wp, a1.x);
            FMA2(acc2[oi][3], wp, a1.y);
        }
    }
    __syncthreads();   // done reading xs/wt

    #pragma unroll
    for (int oi = 0; oi < 4; oi++) {
        int o = ot * 4 + oi;
        #pragma unroll
        for (int pj = 0; pj < 4; pj++)
            *reinterpret_cast<ull*>(&qs[o * 68 + pt * 8 + 2 * pj]) = acc2[oi][pj];
    }
    __syncthreads();

    if (tid < 192) {
        const int arr = tid >> 6;       // 0,1,2
        const int px  = tid & 63;
        const int p   = p0 + px;
        float vv[64];
        #pragma unroll
        for (int j = 0; j < 64; j++)
            vv[j] = qs[(arr * 64 + j) * 68 + px] + qkvb[arr * 64 + j];

        if (arr < 2) {
            float mean = 0.f;
            #pragma unroll
            for (int j = 0; j < 64; j++) mean += vv[j];
            mean *= (1.f / 64);
            float var = 0.f;
            #pragma unroll
            for (int j = 0; j < 64; j++) { float d = vv[j] - mean; var += d * d; }
            float inv = rsqrtf(var * (1.f / 64) + LNEPS);
            const float* lw = arr ? knw : qnw;
            const float* lb = arr ? knb : qnb;
            float sc = arr ? 1.0f : QSCALE;
            #pragma unroll
            for (int j = 0; j < 64; j++)
                vv[j] = ((vv[j] - mean) * inv * lw[j] + lb[j]) * sc;
        }
        if (arr == 0) {
            #pragma unroll
            for (int h8 = 0; h8 < 8; h8++) {
                float4* d4 = reinterpret_cast<float4*>(&g_q[(h8 * NPIX + p) * 8]);
                d4[0] = make_float4(vv[h8*8+0], vv[h8*8+1], vv[h8*8+2], vv[h8*8+3]);
                d4[1] = make_float4(vv[h8*8+4], vv[h8*8+5], vv[h8*8+6], vv[h8*8+7]);
            }
        } else {
            unsigned short* dst = (arr == 1) ? g_kb : g_vb;
            #pragma unroll
            for (int h8 = 0; h8 < 8; h8++) {
                uint4 u;
                u.x = packbf(vv[h8*8+0], vv[h8*8+1]);
                u.y = packbf(vv[h8*8+2], vv[h8*8+3]);
                u.z = packbf(vv[h8*8+4], vv[h8*8+5]);
                u.w = packbf(vv[h8*8+6], vv[h8*8+7]);
                *reinterpret_cast<uint4*>(&dst[(h8 * NPIX + p) * 8]) = u;
            }
        }
    }
}

// =================================================================
// Kernel B: neighborhood attention, bf16 K/V halo, 4-px quads
// =================================================================
static constexpr int HS_B = 67;                       // halo row stride (uint4)
static constexpr int PL_B = 44 * HS_B;                // plane (uint4)
static constexpr int SMEM_B = 2 * PL_B * 16;          // 94336 B

__device__ __forceinline__ int bswz(int c) { return c ^ (((c >> 4) & 1) << 2); }

__global__ void __launch_bounds__(128)
kB()
{
    extern __shared__ uint4 smu[];   // [0..PL_B) = K, [PL_B..2PL_B) = V
    const int tile = blockIdx.x, head = blockIdx.y;
    const int th0 = (tile >> 2) * 16, tw0 = (tile & 3) * 32;
    const int tid = threadIdx.x;
    const unsigned short* kg = g_kb + head * (NPIX * 8);
    const unsigned short* vg = g_vb + head * (NPIX * 8);

    for (int e = tid; e < 2 * 44 * 60; e += 128) {
        int arr = (e >= 44 * 60) ? 1 : 0;
        int i = e - arr * (44 * 60);
        int r = i / 60, col = i - r * 60;
        int hh = min(max(th0 - 16 + r, 0), 127);
        int ww = min(max(tw0 - 16 + col, 0), 127);
        const unsigned short* src = arr ? vg : kg;
        smu[arr * PL_B + r * HS_B + bswz(col)] =
            *reinterpret_cast<const uint4*>(src + (hh * 128 + ww) * 8);
    }
    __syncthreads();

    const int qy   = tid >> 3;
    const int qx8  = tid & 7;
    const int wloc = (qx8 & 3) + ((qx8 >> 2) << 4);
    const int h  = th0 + qy;
    const int wb = tw0 + wloc;

    ulonglong2 qA[4], qB[4];
    #pragma unroll
    for (int t = 0; t < 4; t++) {
        const float* qp = &g_q[(head * NPIX + h * 128 + wb + 4 * t) * 8];
        qA[t] = *reinterpret_cast<const ulonglong2*>(qp);
        qB[t] = *reinterpret_cast<const ulonglong2*>(qp + 4);
    }

    float l[4] = {0.f, 0.f, 0.f, 0.f};
    ull acc2[4][4];
    #pragma unroll
    for (int t = 0; t < 4; t++)
        #pragma unroll
        for (int i = 0; i < 4; i++) acc2[t][i] = 0ull;

    #pragma unroll
    for (int a = 0; a < 8; a++) {
        int oh = 4 * a - 16;
        bool vr = (unsigned)(h + oh) < 128u;
        int rbase = (qy + 16 + oh) * HS_B;
        #pragma unroll
        for (int s = 0; s < 11; s++) {
            int off = rbase + bswz(wloc + 4 * s);
            bool ok = vr && ((unsigned)(wb + 4 * s - 16) < 128u);
            uint4 ku = smu[off];
            uint4 vu = smu[PL_B + off];
            ull kp0 = b2u(ku.x), kp1 = b2u(ku.y), kp2 = b2u(ku.z), kp3 = b2u(ku.w);
            ull vp0 = b2u(vu.x), vp1 = b2u(vu.y), vp2 = b2u(vu.z), vp3 = b2u(vu.w);
            #pragma unroll
            for (int t = 0; t < 4; t++) {
                if (t > s || t < s - 7) continue;
                ull s2 = 0ull;
                FMA2(s2, kp0, qA[t].x);
                FMA2(s2, kp1, qA[t].y);
                FMA2(s2, kp2, qB[t].x);
                FMA2(s2, kp3, qB[t].y);
                float2 sf = upk(s2);
                float sc = ok ? (sf.x + sf.y) : -1e30f;
                float ee = __expf(sc);
                l[t] += ee;
                ull e2 = pk(ee, ee);
                FMA2(acc2[t][0], vp0, e2);
                FMA2(acc2[t][1], vp1, e2);
                FMA2(acc2[t][2], vp2, e2);
                FMA2(acc2[t][3], vp3, e2);
            }
        }
    }
    #pragma unroll
    for (int t = 0; t < 4; t++) {
        float rl = 1.0f / l[t];
        int p = h * 128 + wb + 4 * t;
        #pragma unroll
        for (int i = 0; i < 4; i++) {
            float2 f = upk(acc2[t][i]);
            g_att[(head * 8 + 2 * i)     * NPIX + p] = f.x * rl;
            g_att[(head * 8 + 2 * i + 1) * NPIX + p] = f.y * rl;
        }
    }
}

// =================================================================
// Kernel C: proj GEMM + residual + LN2.  128 thr = 16 ot(4out) x 8 pt(8px)
// =================================================================
static constexpr int SMEM_C = (64 * 68 + 64 * 68) * 4;   // 34816

__global__ void __launch_bounds__(128, 6)
kC(const float* __restrict__ x, const float* __restrict__ projw, const float* __restrict__ projb,
   const float* __restrict__ g1, const float* __restrict__ n2w, const float* __restrict__ n2b)
{
    extern __shared__ float sm[];
    float* as = sm;               // [64][68]
    float* wt = sm + 64 * 68;     // [64][68]
    float* rsum = sm;             // reused: [64][17]
    float* rsq  = sm + 1088;
    float* mv   = sm + 2176;
    float* iv   = sm + 2240;
    const int tid = threadIdx.x;
    const int ot = tid >> 3, pt = tid & 7;
    const int p0 = blockIdx.x * 64;

    for (int i = tid; i < 64 * 64; i += 128) {
        int o = i >> 6, c = i & 63;
        wt[c * 68 + o] = projw[i];
    }
    for (int i = tid; i < 64 * 64; i += 128) {
        int c = i >> 6, pp = i & 63;
        as[c * 68 + pp] = g_att[c * NPIX + p0 + pp];
    }
    __syncthreads();

    ull acc2[4][4];
    #pragma unroll
    for (int oi = 0; oi < 4; oi++)
        #pragma unroll
        for (int pj = 0; pj < 4; pj++) acc2[oi][pj] = 0ull;

    #pragma unroll 2
    for (int c = 0; c < 64; c++) {
        float4 w = *reinterpret_cast<const float4*>(&wt[c * 68 + ot * 4]);
        ulonglong2 a0 = *reinterpret_cast<const ulonglong2*>(&as[c * 68 + pt * 8]);
        ulonglong2 a1 = *reinterpret_cast<const ulonglong2*>(&as[c * 68 + pt * 8 + 4]);
        float wf[4] = {w.x, w.y, w.z, w.w};
        #pragma unroll
        for (int oi = 0; oi < 4; oi++) {
            ull wp = pk(wf[oi], wf[oi]);
            FMA2(acc2[oi][0], wp, a0.x);
            FMA2(acc2[oi][1], wp, a0.y);
            FMA2(acc2[oi][2], wp, a1.x);
            FMA2(acc2[oi][3], wp, a1.y);
        }
    }
    __syncthreads();   // done with as/wt

    float x1v[4][8];
    float ps[8], pq[8];
    #pragma unroll
    for (int j = 0; j < 8; j++) { ps[j] = 0.f; pq[j] = 0.f; }
    #pragma unroll
    for (int oi = 0; oi < 4; oi++) {
        int ch = ot * 4 + oi;
        float pb = projb[ch], gg = g1[ch];
        const float* xr = &x[ch * NPIX + p0 + pt * 8];
        float4 x0 = *reinterpret_cast<const float4*>(xr);
        float4 x1 = *reinterpret_cast<const float4*>(xr + 4);
        float xf[8] = {x0.x, x0.y, x0.z, x0.w, x1.x, x1.y, x1.z, x1.w};
        #pragma unroll
        for (int pj = 0; pj < 4; pj++) {
            float2 f = upk(acc2[oi][pj]);
            float v0 = xf[2*pj]   + gg * (f.x + pb);
            float v1 = xf[2*pj+1] + gg * (f.y + pb);
            x1v[oi][2*pj] = v0; x1v[oi][2*pj+1] = v1;
            ps[2*pj] += v0;  ps[2*pj+1] += v1;
            pq[2*pj] += v0 * v0; pq[2*pj+1] += v1 * v1;
        }
        float4* d4 = reinterpret_cast<float4*>(&g_x1[ch * NPIX + p0 + pt * 8]);
        d4[0] = make_float4(x1v[oi][0], x1v[oi][1], x1v[oi][2], x1v[oi][3]);
        d4[1] = make_float4(x1v[oi][4], x1v[oi][5], x1v[oi][6], x1v[oi][7]);
    }
    #pragma unroll
    for (int j = 0; j < 8; j++) {
        rsum[(pt * 8 + j) * 17 + ot] = ps[j];
        rsq [(pt * 8 + j) * 17 + ot] = pq[j];
    }
    __syncthreads();
    if (tid < 64) {
        float s = 0.f, q = 0.f;
        #pragma unroll
        for (int k = 0; k < 16; k++) { s += rsum[tid * 17 + k]; q += rsq[tid * 17 + k]; }
        float mean = s * (1.f / 64);
        float var = q * (1.f / 64) - mean * mean;
        mv[tid] = mean;
        iv[tid] = rsqrtf(var + LNEPS);
    }
    __syncthreads();
    float mj[8], ij[8];
    #pragma unroll
    for (int j = 0; j < 8; j++) { mj[j] = mv[pt * 8 + j]; ij[j] = iv[pt * 8 + j]; }
    #pragma unroll
    for (int oi = 0; oi < 4; oi++) {
        int ch = ot * 4 + oi;
        float nw = n2w[ch], nb = n2b[ch];
        float y[8];
        #pragma unroll
        for (int j = 0; j < 8; j++) y[j] = (x1v[oi][j] - mj[j]) * ij[j] * nw + nb;
        float4* d4 = reinterpret_cast<float4*>(&g_y[ch * NPIX + p0 + pt * 8]);
        d4[0] = make_float4(y[0], y[1], y[2], y[3]);
        d4[1] = make_float4(y[4], y[5], y[6], y[7]);
    }
}

// =================================================================
// Kernel D: fc1 GEMM + LN + SiLU.  256 thr = 32 ot(4out) x 8 pt(8px)
// =================================================================
static constexpr int SMEM_D = (64 * 68 + 64 * 132) * 4;   // 51200

__global__ void __launch_bounds__(256, 3)
kD(const float* __restrict__ fc1w, const float* __restrict__ fc1b,
   const float* __restrict__ mnw, const float* __restrict__ mnb)
{
    extern __shared__ float sm[];
    float* ys = sm;               // [64][68]
    float* wt = sm + 64 * 68;     // [64][132]
    float* rsum = sm;             // reused: [64][33]
    float* rsq  = sm + 2112;
    float* mv   = sm + 4224;
    float* iv   = sm + 4288;
    const int tid = threadIdx.x;
    const int ot = tid >> 3, pt = tid & 7;
    const int p0 = blockIdx.x * 64;

    for (int i = tid; i < 128 * 64; i += 256) {
        int o = i >> 6, c = i & 63;
        wt[c * 132 + o] = fc1w[i];
    }
    for (int i = tid; i < 64 * 64; i += 256) {
        int c = i >> 6, pp = i & 63;
        ys[c * 68 + pp] = g_y[c * NPIX + p0 + pp];
    }
    __syncthreads();

    ull acc2[4][4];
    #pragma unroll
    for (int oi = 0; oi < 4; oi++)
        #pragma unroll
        for (int pj = 0; pj < 4; pj++) acc2[oi][pj] = 0ull;

    #pragma unroll 2
    for (int c = 0; c < 64; c++) {
        float4 w = *reinterpret_cast<const float4*>(&wt[c * 132 + ot * 4]);
        ulonglong2 a0 = *reinterpret_cast<const ulonglong2*>(&ys[c * 68 + pt * 8]);
        ulonglong2 a1 = *reinterpret_cast<const ulonglong2*>(&ys[c * 68 + pt * 8 + 4]);
        float wf[4] = {w.x, w.y, w.z, w.w};
        #pragma unroll
        for (int oi = 0; oi < 4; oi++) {
            ull wp = pk(wf[oi], wf[oi]);
            FMA2(acc2[oi][0], wp, a0.x);
            FMA2(acc2[oi][1], wp, a0.y);
            FMA2(acc2[oi][2], wp, a1.x);
            FMA2(acc2[oi][3], wp, a1.y);
        }
    }
    __syncthreads();

    float hv[4][8];
    float ps[8], pq[8];
    #pragma unroll
    for (int j = 0; j < 8; j++) { ps[j] = 0.f; pq[j] = 0.f; }
    #pragma unroll
    for (int oi = 0; oi < 4; oi++) {
        float fb = fc1b[ot * 4 + oi];
        #pragma unroll
        for (int pj = 0; pj < 4; pj++) {
            float2 f = upk(acc2[oi][pj]);
            float v0 = f.x + fb, v1 = f.y + fb;
            hv[oi][2*pj] = v0; hv[oi][2*pj+1] = v1;
            ps[2*pj] += v0;  ps[2*pj+1] += v1;
            pq[2*pj] += v0 * v0; pq[2*pj+1] += v1 * v1;
        }
    }
    #pragma unroll
    for (int j = 0; j < 8; j++) {
        rsum[(pt * 8 + j) * 33 + ot] = ps[j];
        rsq [(pt * 8 + j) * 33 + ot] = pq[j];
    }
    __syncthreads();
    if (tid < 64) {
        float s = 0.f, q = 0.f;
        #pragma unroll
        for (int k = 0; k < 32; k++) { s += rsum[tid * 33 + k]; q += rsq[tid * 33 + k]; }
        float mean = s * (1.f / 128);
        float var = q * (1.f / 128) - mean * mean;
        mv[tid] = mean;
        iv[tid] = rsqrtf(var + LNEPS);
    }
    __syncthreads();
    float mj[8], ij[8];
    #pragma unroll
    for (int j = 0; j < 8; j++) { mj[j] = mv[pt * 8 + j]; ij[j] = iv[pt * 8 + j]; }
    #pragma unroll
    for (int oi = 0; oi < 4; oi++) {
        int ch = ot * 4 + oi;
        float nw = mnw[ch], nb = mnb[ch];
        float o8[8];
        #pragma unroll
        for (int j = 0; j < 8; j++) {
            float hh = (hv[oi][j] - mj[j]) * ij[j] * nw + nb;
            o8[j] = hh / (1.f + __expf(-hh));
        }
        float4* d4 = reinterpret_cast<float4*>(&g_h1[ch * NPIX + p0 + pt * 8]);
        d4[0] = make_float4(o8[0], o8[1], o8[2], o8[3]);
        d4[1] = make_float4(o8[4], o8[5], o8[6], o8[7]);
    }
}

// =================================================================
// Kernel E: fc2 GEMM + residual -> out.  256 thr = 16 ot(4out) x 16 pt(4px)
// =================================================================
static constexpr int SMEM_E = (128 * 68 + 128 * 68) * 4;   // 69632

__global__ void __launch_bounds__(256, 3)
kE(const float* __restrict__ fc2w, const float* __restrict__ fc2b,
   const float* __restrict__ g2, float* __restrict__ out)
{
    extern __shared__ float sm[];
    float* hs = sm;                // [128][68]
    float* wt = sm + 128 * 68;     // [128][68]
    const int tid = threadIdx.x;
    const int ot = tid >> 4, pt = tid & 15;
    const int p0 = blockIdx.x * 64;

    for (int i = tid; i < 64 * 128; i += 256) {
        int o = i >> 7, c = i & 127;
        wt[c * 68 + o] = fc2w[i];
    }
    for (int i = tid; i < 128 * 64; i += 256) {
        int c = i >> 6, pp = i & 63;
        hs[c * 68 + pp] = g_h1[c * NPIX + p0 + pp];
    }
    __syncthreads();

    ull acc2[4][2];
    #pragma unroll
    for (int oi = 0; oi < 4; oi++) { acc2[oi][0] = 0ull; acc2[oi][1] = 0ull; }

    #pragma unroll 4
    for (int c = 0; c < 128; c++) {
        float4 w = *reinterpret_cast<const float4*>(&wt[c * 68 + ot * 4]);
        ulonglong2 a0 = *reinterpret_cast<const ulonglong2*>(&hs[c * 68 + pt * 4]);
        float wf[4] = {w.x, w.y, w.z, w.w};
        #pragma unroll
        for (int oi = 0; oi < 4; oi++) {
            ull wp = pk(wf[oi], wf[oi]);
            FMA2(acc2[oi][0], wp, a0.x);
            FMA2(acc2[oi][1], wp, a0.y);
        }
    }

    #pragma unroll
    for (int oi = 0; oi < 4; oi++) {
        int ch = ot * 4 + oi;
        float fb = fc2b[ch], gg = g2[ch];
        float4 xr = *reinterpret_cast<const float4*>(&g_x1[ch * NPIX + p0 + pt * 4]);
        float xf[4] = {xr.x, xr.y, xr.z, xr.w};
        float o4[4];
        #pragma unroll
        for (int pj = 0; pj < 2; pj++) {
            float2 f = upk(acc2[oi][pj]);
            o4[2*pj]   = xf[2*pj]   + gg * (f.x + fb);
            o4[2*pj+1] = xf[2*pj+1] + gg * (f.y + fb);
        }
        float4* d4 = reinterpret_cast<float4*>(&out[ch * NPIX + p0 + pt * 4]);
        *d4 = make_float4(o4[0], o4[1], o4[2], o4[3]);
    }
}

// =================================================================
extern "C" void kernel_launch(void* const* d_in, const int* in_sizes, int n_in,
                              void* d_out, int out_size)
{
    const float* x     = (const float*)d_in[0];
    const float* n1w   = (const float*)d_in[1];
    const float* n1b   = (const float*)d_in[2];
    const float* qkvw  = (const float*)d_in[3];
    const float* qkvb  = (const float*)d_in[4];
    const float* qnw   = (const float*)d_in[5];
    const float* qnb   = (const float*)d_in[6];
    const float* knw   = (const float*)d_in[7];
    const float* knb   = (const float*)d_in[8];
    const float* projw = (const float*)d_in[9];
    const float* projb = (const float*)d_in[10];
    const float* g1    = (const float*)d_in[11];
    const float* n2w   = (const float*)d_in[12];
    const float* n2b   = (const float*)d_in[13];
    const float* fc1w  = (const float*)d_in[14];
    const float* fc1b  = (const float*)d_in[15];
    const float* mnw   = (const float*)d_in[16];
    const float* mnb   = (const float*)d_in[17];
    const float* fc2w  = (const float*)d_in[18];
    const float* fc2b  = (const float*)d_in[19];
    const float* g2    = (const float*)d_in[20];
    float* out = (float*)d_out;

    cudaFuncSetAttribute(kA, cudaFuncAttributeMaxDynamicSharedMemorySize, SMEM_A);
    cudaFuncSetAttribute(kB, cudaFuncAttributeMaxDynamicSharedMemorySize, SMEM_B);
    cudaFuncSetAttribute(kC, cudaFuncAttributeMaxDynamicSharedMemorySize, SMEM_C);
    cudaFuncSetAttribute(kD, cudaFuncAttributeMaxDynamicSharedMemorySize, SMEM_D);
    cudaFuncSetAttribute(kE, cudaFuncAttributeMaxDynamicSharedMemorySize, SMEM_E);

    kA<<<256, 384, SMEM_A>>>(x, n1w, n1b, qkvw, qkvb, qnw, qnb, knw, knb);
    kB<<<dim3(32, 8), 128, SMEM_B>>>();
    kC<<<256, 128, SMEM_C>>>(x, projw, projb, g1, n2w, n2b);
    kD<<<256, 256, SMEM_D>>>(fc1w, fc1b, mnw, mnb);
    kE<<<256, 256, SMEM_E>>>(fc2w, fc2b, g2, out);
}

// round 7
// speedup vs baseline: 1.3919x; 1.3919x over previous
#include <cuda_runtime.h>
#include <cuda_bf16.h>

typedef unsigned long long ull;
typedef unsigned int uint;
typedef unsigned short ushort_t;

static constexpr int IMG   = 128;
static constexpr int NPIX  = IMG * IMG;      // 16384
static constexpr int CH    = 64;
static constexpr int NHEAD = 8;
static constexpr int HIDN  = 128;
static constexpr float LNEPS  = 1e-5f;
static constexpr float QSCALE = 0.35355339059327373f;   // 8^-0.5

// ---------------- scratch ----------------
__device__ __align__(16) float    g_q  [NHEAD * NPIX * 8];          // fp32 pixel-major
__device__ __align__(16) ushort_t g_kb [NHEAD * NPIX * 8];          // bf16 pixel-major
__device__ __align__(16) ushort_t g_vb [NHEAD * NPIX * 8];          // bf16 pixel-major
__device__ __align__(16) ushort_t g_attb[CH * NPIX];                // bf16 planar
__device__ __align__(16) float    g_x1 [CH * NPIX];                 // fp32 planar
__device__ __align__(16) ushort_t g_yb [CH * NPIX];                 // bf16 planar
__device__ __align__(16) ushort_t g_h1b[HIDN * NPIX];               // bf16 planar

// ---------------- helpers ----------------
#define FMA2(acc, a, b) asm("fma.rn.f32x2 %0, %1, %2, %0;" : "+l"(acc) : "l"(a), "l"(b))

__device__ __forceinline__ ull pk(float lo, float hi) {
    ull r; asm("mov.b64 %0, {%1, %2};" : "=l"(r) : "f"(lo), "f"(hi)); return r;
}
__device__ __forceinline__ float2 upk(ull v) {
    float2 r; asm("mov.b64 {%0, %1}, %2;" : "=f"(r.x), "=f"(r.y) : "l"(v)); return r;
}
__device__ __forceinline__ uint packbf(float a, float b) {
    __nv_bfloat162 h = __floats2bfloat162_rn(a, b);
    return *reinterpret_cast<uint*>(&h);
}
__device__ __forceinline__ ushort_t bfbits(float v) {
    __nv_bfloat16 b = __float2bfloat16_rn(v);
    return *reinterpret_cast<ushort_t*>(&b);
}
__device__ __forceinline__ ull b2u(uint u) {
    return pk(__uint_as_float(u << 16), __uint_as_float(u & 0xffff0000u));
}
__device__ __forceinline__ uint sptr(const void* p) {
    return (uint)__cvta_generic_to_shared(p);
}
__device__ __forceinline__ void ldsm_x4(uint &r0, uint &r1, uint &r2, uint &r3, uint addr) {
    asm volatile("ldmatrix.sync.aligned.m8n8.x4.shared.b16 {%0,%1,%2,%3}, [%4];"
                 : "=r"(r0), "=r"(r1), "=r"(r2), "=r"(r3) : "r"(addr));
}
__device__ __forceinline__ void ldsm_x2t(uint &r0, uint &r1, uint addr) {
    asm volatile("ldmatrix.sync.aligned.m8n8.x2.trans.shared.b16 {%0,%1}, [%2];"
                 : "=r"(r0), "=r"(r1) : "r"(addr));
}
__device__ __forceinline__ void mma16816(float* c, const uint* a, uint b0, uint b1) {
    asm volatile("mma.sync.aligned.m16n8k16.row.col.f32.bf16.bf16.f32 "
                 "{%0,%1,%2,%3}, {%4,%5,%6,%7}, {%8,%9}, {%0,%1,%2,%3};"
                 : "+f"(c[0]), "+f"(c[1]), "+f"(c[2]), "+f"(c[3])
                 : "r"(a[0]), "r"(a[1]), "r"(a[2]), "r"(a[3]), "r"(b0), "r"(b1));
}

// =================================================================
// Kernel A: LN1 -> QKV MMA GEMM -> qLN/kLN -> q fp32, k/v bf16
// 64-px tiles, grid 256, block 384 (12 warps, one 16-out tile each)
// =================================================================
static constexpr int SMEM_A = 192 * 72 * 2 + 64 * 72 * 2;   // 36864 (stage 34816 aliased)

__global__ void __launch_bounds__(384, 2)
kA(const float* __restrict__ x, const float* __restrict__ n1w, const float* __restrict__ n1b,
   const float* __restrict__ qkvw, const float* __restrict__ qkvb,
   const float* __restrict__ qnw, const float* __restrict__ qnb,
   const float* __restrict__ knw, const float* __restrict__ knb)
{
    extern __shared__ float sm[];
    ushort_t* wbf  = reinterpret_cast<ushort_t*>(sm);          // [192][72]
    ushort_t* actb = wbf + 192 * 72;                           // [64][72]
    float*    stage = sm;                                      // [128][68] aliased
    const int tid = threadIdx.x;
    const int p0 = blockIdx.x * 64;

    // weights -> bf16 smem (A is [o][k] row-major as given)
    for (int i = tid; i < 192 * 64; i += 384) {
        int o = i >> 6, c = i & 63;
        wbf[o * 72 + c] = bfbits(qkvw[i]);
    }
    // LN1 -> act bf16 [c][px]
    if (tid < 256) {
        const int s = tid & 3, px = tid >> 2;
        const int p = p0 + px;
        float xv[16];
        float sum = 0.f, sq = 0.f;
        #pragma unroll
        for (int j = 0; j < 16; j++) {
            float v = x[(s * 16 + j) * NPIX + p];
            xv[j] = v; sum += v; sq += v * v;
        }
        sum += __shfl_xor_sync(0xffffffffu, sum, 1);
        sum += __shfl_xor_sync(0xffffffffu, sum, 2);
        sq  += __shfl_xor_sync(0xffffffffu, sq, 1);
        sq  += __shfl_xor_sync(0xffffffffu, sq, 2);
        float mean = sum * (1.f / 64);
        float inv = rsqrtf(sq * (1.f / 64) - mean * mean + LNEPS);
        #pragma unroll
        for (int j = 0; j < 16; j++) {
            int c = s * 16 + j;
            actb[c * 72 + px] = bfbits((xv[j] - mean) * inv * n1w[c] + n1b[c]);
        }
    }
    __syncthreads();

    const int wid = tid >> 5, lane = tid & 31;
    const int gid = lane >> 2, tig = lane & 3;
    const int q4 = lane >> 3, r4 = lane & 7;
    const int lr = lane & 15;
    const int m0 = wid * 16;

    uint a[4][4];
    #pragma unroll
    for (int ks = 0; ks < 4; ks++) {
        int arow = m0 + r4 + ((q4 & 1) << 3);
        int acol = ks * 16 + ((q4 >> 1) << 3);
        ldsm_x4(a[ks][0], a[ks][1], a[ks][2], a[ks][3], sptr(&wbf[arow * 72 + acol]));
    }
    float c[8][4];
    #pragma unroll
    for (int nt = 0; nt < 8; nt++)
        #pragma unroll
        for (int i = 0; i < 4; i++) c[nt][i] = 0.f;

    #pragma unroll
    for (int nt = 0; nt < 8; nt++) {
        #pragma unroll
        for (int ks = 0; ks < 4; ks++) {
            uint b0, b1;
            ldsm_x2t(b0, b1, sptr(&actb[(ks * 16 + lr) * 72 + nt * 8]));
            mma16816(c[nt], a[ks], b0, b1);
        }
    }
    __syncthreads();

    // stage q+k (warps 0-7 = outs 0-127)
    if (wid < 8) {
        #pragma unroll
        for (int nt = 0; nt < 8; nt++) {
            int col = nt * 8 + 2 * tig;
            *reinterpret_cast<float2*>(&stage[(m0 + gid) * 68 + col])     = make_float2(c[nt][0], c[nt][1]);
            *reinterpret_cast<float2*>(&stage[(m0 + 8 + gid) * 68 + col]) = make_float2(c[nt][2], c[nt][3]);
        }
    }
    __syncthreads();

    if (tid < 256) {
        const int s = tid & 3, px = tid >> 2;
        const int p = p0 + px;
        // ---- Q ----
        {
            float vv[16];
            float sum = 0.f, sq = 0.f;
            #pragma unroll
            for (int j = 0; j < 16; j++) {
                float v = stage[(s * 16 + j) * 68 + px] + qkvb[s * 16 + j];
                vv[j] = v; sum += v; sq += v * v;
            }
            sum += __shfl_xor_sync(0xffffffffu, sum, 1);
            sum += __shfl_xor_sync(0xffffffffu, sum, 2);
            sq  += __shfl_xor_sync(0xffffffffu, sq, 1);
            sq  += __shfl_xor_sync(0xffffffffu, sq, 2);
            float mean = sum * (1.f / 64);
            float inv = rsqrtf(sq * (1.f / 64) - mean * mean + LNEPS);
            #pragma unroll
            for (int j = 0; j < 16; j++) {
                int ch = s * 16 + j;
                vv[j] = ((vv[j] - mean) * inv * qnw[ch] + qnb[ch]) * QSCALE;
            }
            float4* d0 = reinterpret_cast<float4*>(&g_q[((2 * s) * NPIX + p) * 8]);
            d0[0] = make_float4(vv[0], vv[1], vv[2], vv[3]);
            d0[1] = make_float4(vv[4], vv[5], vv[6], vv[7]);
            float4* d1 = reinterpret_cast<float4*>(&g_q[((2 * s + 1) * NPIX + p) * 8]);
            d1[0] = make_float4(vv[8], vv[9], vv[10], vv[11]);
            d1[1] = make_float4(vv[12], vv[13], vv[14], vv[15]);
        }
        // ---- K ----
        {
            float vv[16];
            float sum = 0.f, sq = 0.f;
            #pragma unroll
            for (int j = 0; j < 16; j++) {
                float v = stage[(64 + s * 16 + j) * 68 + px] + qkvb[64 + s * 16 + j];
                vv[j] = v; sum += v; sq += v * v;
            }
            sum += __shfl_xor_sync(0xffffffffu, sum, 1);
            sum += __shfl_xor_sync(0xffffffffu, sum, 2);
            sq  += __shfl_xor_sync(0xffffffffu, sq, 1);
            sq  += __shfl_xor_sync(0xffffffffu, sq, 2);
            float mean = sum * (1.f / 64);
            float inv = rsqrtf(sq * (1.f / 64) - mean * mean + LNEPS);
            #pragma unroll
            for (int j = 0; j < 16; j++) {
                int ch = s * 16 + j;
                vv[j] = (vv[j] - mean) * inv * knw[ch] + knb[ch];
            }
            uint4 u0, u1;
            u0.x = packbf(vv[0], vv[1]);  u0.y = packbf(vv[2], vv[3]);
            u0.z = packbf(vv[4], vv[5]);  u0.w = packbf(vv[6], vv[7]);
            u1.x = packbf(vv[8], vv[9]);  u1.y = packbf(vv[10], vv[11]);
            u1.z = packbf(vv[12], vv[13]); u1.w = packbf(vv[14], vv[15]);
            *reinterpret_cast<uint4*>(&g_kb[((2 * s) * NPIX + p) * 8])     = u0;
            *reinterpret_cast<uint4*>(&g_kb[((2 * s + 1) * NPIX + p) * 8]) = u1;
        }
    }
    __syncthreads();

    // stage v (warps 8-11)
    if (wid >= 8) {
        int mv0 = (wid - 8) * 16;
        #pragma unroll
        for (int nt = 0; nt < 8; nt++) {
            int col = nt * 8 + 2 * tig;
            *reinterpret_cast<float2*>(&stage[(mv0 + gid) * 68 + col])     = make_float2(c[nt][0], c[nt][1]);
            *reinterpret_cast<float2*>(&stage[(mv0 + 8 + gid) * 68 + col]) = make_float2(c[nt][2], c[nt][3]);
        }
    }
    __syncthreads();

    if (tid < 256) {
        const int s = tid & 3, px = tid >> 2;
        const int p = p0 + px;
        float vv[16];
        #pragma unroll
        for (int j = 0; j < 16; j++)
            vv[j] = stage[(s * 16 + j) * 68 + px] + qkvb[128 + s * 16 + j];
        uint4 u0, u1;
        u0.x = packbf(vv[0], vv[1]);  u0.y = packbf(vv[2], vv[3]);
        u0.z = packbf(vv[4], vv[5]);  u0.w = packbf(vv[6], vv[7]);
        u1.x = packbf(vv[8], vv[9]);  u1.y = packbf(vv[10], vv[11]);
        u1.z = packbf(vv[12], vv[13]); u1.w = packbf(vv[14], vv[15]);
        *reinterpret_cast<uint4*>(&g_vb[((2 * s) * NPIX + p) * 8])     = u0;
        *reinterpret_cast<uint4*>(&g_vb[((2 * s + 1) * NPIX + p) * 8]) = u1;
    }
}

// =================================================================
// Kernel B: neighborhood attention, bf16 K/V halo, 4-px quads
// (unchanged from R5 except bf16 att output)
// =================================================================
static constexpr int HS_B = 67;                       // halo row stride (uint4)
static constexpr int PL_B = 44 * HS_B;                // plane (uint4)
static constexpr int SMEM_B = 2 * PL_B * 16;          // 94336 B

__device__ __forceinline__ int bswz(int c) { return c ^ (((c >> 4) & 1) << 2); }

__global__ void __launch_bounds__(128)
kB()
{
    extern __shared__ uint4 smu[];
    const int tile = blockIdx.x, head = blockIdx.y;
    const int th0 = (tile >> 2) * 16, tw0 = (tile & 3) * 32;
    const int tid = threadIdx.x;
    const ushort_t* kg = g_kb + head * (NPIX * 8);
    const ushort_t* vg = g_vb + head * (NPIX * 8);

    for (int e = tid; e < 2 * 44 * 60; e += 128) {
        int arr = (e >= 44 * 60) ? 1 : 0;
        int i = e - arr * (44 * 60);
        int r = i / 60, col = i - r * 60;
        int hh = min(max(th0 - 16 + r, 0), 127);
        int ww = min(max(tw0 - 16 + col, 0), 127);
        const ushort_t* src = arr ? vg : kg;
        smu[arr * PL_B + r * HS_B + bswz(col)] =
            *reinterpret_cast<const uint4*>(src + (hh * 128 + ww) * 8);
    }
    __syncthreads();

    const int qy   = tid >> 3;
    const int qx8  = tid & 7;
    const int wloc = (qx8 & 3) + ((qx8 >> 2) << 4);
    const int h  = th0 + qy;
    const int wb = tw0 + wloc;

    ulonglong2 qA[4], qB[4];
    #pragma unroll
    for (int t = 0; t < 4; t++) {
        const float* qp = &g_q[(head * NPIX + h * 128 + wb + 4 * t) * 8];
        qA[t] = *reinterpret_cast<const ulonglong2*>(qp);
        qB[t] = *reinterpret_cast<const ulonglong2*>(qp + 4);
    }

    float l[4] = {0.f, 0.f, 0.f, 0.f};
    ull acc2[4][4];
    #pragma unroll
    for (int t = 0; t < 4; t++)
        #pragma unroll
        for (int i = 0; i < 4; i++) acc2[t][i] = 0ull;

    #pragma unroll
    for (int a = 0; a < 8; a++) {
        int oh = 4 * a - 16;
        bool vr = (unsigned)(h + oh) < 128u;
        int rbase = (qy + 16 + oh) * HS_B;
        #pragma unroll
        for (int s = 0; s < 11; s++) {
            int off = rbase + bswz(wloc + 4 * s);
            bool ok = vr && ((unsigned)(wb + 4 * s - 16) < 128u);
            uint4 ku = smu[off];
            uint4 vu = smu[PL_B + off];
            ull kp0 = b2u(ku.x), kp1 = b2u(ku.y), kp2 = b2u(ku.z), kp3 = b2u(ku.w);
            ull vp0 = b2u(vu.x), vp1 = b2u(vu.y), vp2 = b2u(vu.z), vp3 = b2u(vu.w);
            #pragma unroll
            for (int t = 0; t < 4; t++) {
                if (t > s || t < s - 7) continue;
                ull s2 = 0ull;
                FMA2(s2, kp0, qA[t].x);
                FMA2(s2, kp1, qA[t].y);
                FMA2(s2, kp2, qB[t].x);
                FMA2(s2, kp3, qB[t].y);
                float2 sf = upk(s2);
                float sc = ok ? (sf.x + sf.y) : -1e30f;
                float ee = __expf(sc);
                l[t] += ee;
                ull e2 = pk(ee, ee);
                FMA2(acc2[t][0], vp0, e2);
                FMA2(acc2[t][1], vp1, e2);
                FMA2(acc2[t][2], vp2, e2);
                FMA2(acc2[t][3], vp3, e2);
            }
        }
    }
    #pragma unroll
    for (int t = 0; t < 4; t++) {
        float rl = 1.0f / l[t];
        int p = h * 128 + wb + 4 * t;
        #pragma unroll
        for (int i = 0; i < 4; i++) {
            float2 f = upk(acc2[t][i]);
            g_attb[(head * 8 + 2 * i)     * NPIX + p] = bfbits(f.x * rl);
            g_attb[(head * 8 + 2 * i + 1) * NPIX + p] = bfbits(f.y * rl);
        }
    }
}

// =================================================================
// Kernel C: proj MMA + residual + LN2.  128 thr (4 warps), grid 256
// =================================================================
static constexpr int SMEM_C = 64 * 72 * 2 * 2;   // 18432 (stage 17408 aliased)

__global__ void __launch_bounds__(128, 4)
kC(const float* __restrict__ x, const float* __restrict__ projw, const float* __restrict__ projb,
   const float* __restrict__ g1, const float* __restrict__ n2w, const float* __restrict__ n2b)
{
    extern __shared__ float sm[];
    ushort_t* wbf  = reinterpret_cast<ushort_t*>(sm);   // [64][72]
    ushort_t* actb = wbf + 64 * 72;                     // [64][72]
    float*    stage = sm;                               // [64][68] aliased
    const int tid = threadIdx.x;
    const int p0 = blockIdx.x * 64;

    for (int i = tid; i < 64 * 64; i += 128) {
        int o = i >> 6, c = i & 63;
        wbf[o * 72 + c] = bfbits(projw[i]);
    }
    for (int i = tid; i < 64 * 32; i += 128) {
        int c = i >> 5, u = i & 31;
        *reinterpret_cast<uint*>(&actb[c * 72 + 2 * u]) =
            *reinterpret_cast<const uint*>(&g_attb[c * NPIX + p0 + 2 * u]);
    }
    __syncthreads();

    const int wid = tid >> 5, lane = tid & 31;
    const int gid = lane >> 2, tig = lane & 3;
    const int q4 = lane >> 3, r4 = lane & 7;
    const int lr = lane & 15;
    const int m0 = wid * 16;

    uint a[4][4];
    #pragma unroll
    for (int ks = 0; ks < 4; ks++) {
        int arow = m0 + r4 + ((q4 & 1) << 3);
        int acol = ks * 16 + ((q4 >> 1) << 3);
        ldsm_x4(a[ks][0], a[ks][1], a[ks][2], a[ks][3], sptr(&wbf[arow * 72 + acol]));
    }
    float c[8][4];
    #pragma unroll
    for (int nt = 0; nt < 8; nt++)
        #pragma unroll
        for (int i = 0; i < 4; i++) c[nt][i] = 0.f;
    #pragma unroll
    for (int nt = 0; nt < 8; nt++) {
        #pragma unroll
        for (int ks = 0; ks < 4; ks++) {
            uint b0, b1;
            ldsm_x2t(b0, b1, sptr(&actb[(ks * 16 + lr) * 72 + nt * 8]));
            mma16816(c[nt], a[ks], b0, b1);
        }
    }
    __syncthreads();
    #pragma unroll
    for (int nt = 0; nt < 8; nt++) {
        int col = nt * 8 + 2 * tig;
        *reinterpret_cast<float2*>(&stage[(m0 + gid) * 68 + col])     = make_float2(c[nt][0], c[nt][1]);
        *reinterpret_cast<float2*>(&stage[(m0 + 8 + gid) * 68 + col]) = make_float2(c[nt][2], c[nt][3]);
    }
    __syncthreads();

    // epilogue: 2 lanes per pixel, 32 outs each
    const int s = tid & 1, px = tid >> 1;
    const int p = p0 + px;
    float vv[32];
    float sum = 0.f, sq = 0.f;
    #pragma unroll
    for (int j = 0; j < 32; j++) {
        int ch = s * 32 + j;
        float v = x[ch * NPIX + p] + g1[ch] * (stage[ch * 68 + px] + projb[ch]);
        g_x1[ch * NPIX + p] = v;
        vv[j] = v; sum += v; sq += v * v;
    }
    sum += __shfl_xor_sync(0xffffffffu, sum, 1);
    sq  += __shfl_xor_sync(0xffffffffu, sq, 1);
    float mean = sum * (1.f / 64);
    float inv = rsqrtf(sq * (1.f / 64) - mean * mean + LNEPS);
    #pragma unroll
    for (int j = 0; j < 32; j++) {
        int ch = s * 32 + j;
        g_yb[ch * NPIX + p] = bfbits((vv[j] - mean) * inv * n2w[ch] + n2b[ch]);
    }
}

// =================================================================
// Kernel D: fc1 MMA + LN + SiLU.  256 thr (8 warps), grid 256
// =================================================================
static constexpr int SMEM_D = 128 * 68 * 4;   // 34816 (gemm phase 27648 aliased)

__global__ void __launch_bounds__(256, 3)
kD(const float* __restrict__ fc1w, const float* __restrict__ fc1b,
   const float* __restrict__ mnw, const float* __restrict__ mnb)
{
    extern __shared__ float sm[];
    ushort_t* wbf  = reinterpret_cast<ushort_t*>(sm);   // [128][72]
    ushort_t* actb = wbf + 128 * 72;                    // [64][72]
    float*    stage = sm;                               // [128][68] aliased
    const int tid = threadIdx.x;
    const int p0 = blockIdx.x * 64;

    for (int i = tid; i < 128 * 64; i += 256) {
        int o = i >> 6, c = i & 63;
        wbf[o * 72 + c] = bfbits(fc1w[i]);
    }
    for (int i = tid; i < 64 * 32; i += 256) {
        int c = i >> 5, u = i & 31;
        *reinterpret_cast<uint*>(&actb[c * 72 + 2 * u]) =
            *reinterpret_cast<const uint*>(&g_yb[c * NPIX + p0 + 2 * u]);
    }
    __syncthreads();

    const int wid = tid >> 5, lane = tid & 31;
    const int gid = lane >> 2, tig = lane & 3;
    const int q4 = lane >> 3, r4 = lane & 7;
    const int lr = lane & 15;
    const int m0 = wid * 16;

    uint a[4][4];
    #pragma unroll
    for (int ks = 0; ks < 4; ks++) {
        int arow = m0 + r4 + ((q4 & 1) << 3);
        int acol = ks * 16 + ((q4 >> 1) << 3);
        ldsm_x4(a[ks][0], a[ks][1], a[ks][2], a[ks][3], sptr(&wbf[arow * 72 + acol]));
    }
    float c[8][4];
    #pragma unroll
    for (int nt = 0; nt < 8; nt++)
        #pragma unroll
        for (int i = 0; i < 4; i++) c[nt][i] = 0.f;
    #pragma unroll
    for (int nt = 0; nt < 8; nt++) {
        #pragma unroll
        for (int ks = 0; ks < 4; ks++) {
            uint b0, b1;
            ldsm_x2t(b0, b1, sptr(&actb[(ks * 16 + lr) * 72 + nt * 8]));
            mma16816(c[nt], a[ks], b0, b1);
        }
    }
    __syncthreads();
    #pragma unroll
    for (int nt = 0; nt < 8; nt++) {
        int col = nt * 8 + 2 * tig;
        *reinterpret_cast<float2*>(&stage[(m0 + gid) * 68 + col])     = make_float2(c[nt][0], c[nt][1]);
        *reinterpret_cast<float2*>(&stage[(m0 + 8 + gid) * 68 + col]) = make_float2(c[nt][2], c[nt][3]);
    }
    __syncthreads();

    // epilogue: 4 lanes per pixel, 32 outs each; LN over 128 + SiLU
    const int s = tid & 3, px = tid >> 2;
    const int p = p0 + px;
    float vv[32];
    float sum = 0.f, sq = 0.f;
    #pragma unroll
    for (int j = 0; j < 32; j++) {
        int ch = s * 32 + j;
        float v = stage[ch * 68 + px] + fc1b[ch];
        vv[j] = v; sum += v; sq += v * v;
    }
    sum += __shfl_xor_sync(0xffffffffu, sum, 1);
    sum += __shfl_xor_sync(0xffffffffu, sum, 2);
    sq  += __shfl_xor_sync(0xffffffffu, sq, 1);
    sq  += __shfl_xor_sync(0xffffffffu, sq, 2);
    float mean = sum * (1.f / 128);
    float inv = rsqrtf(sq * (1.f / 128) - mean * mean + LNEPS);
    #pragma unroll
    for (int j = 0; j < 32; j++) {
        int ch = s * 32 + j;
        float hh = (vv[j] - mean) * inv * mnw[ch] + mnb[ch];
        g_h1b[ch * NPIX + p] = bfbits(hh / (1.f + __expf(-hh)));
    }
}

// =================================================================
// Kernel E: fc2 MMA + residual -> out.  128 thr (4 warps), grid 256
// =================================================================
static constexpr int SMEM_E = 64 * 136 * 2 + 128 * 72 * 2;   // 35840

__global__ void __launch_bounds__(128, 4)
kE(const float* __restrict__ fc2w, const float* __restrict__ fc2b,
   const float* __restrict__ g2, float* __restrict__ out)
{
    extern __shared__ float sm[];
    ushort_t* wbf  = reinterpret_cast<ushort_t*>(sm);   // [64][136]
    ushort_t* actb = wbf + 64 * 136;                    // [128][72]
    const int tid = threadIdx.x;
    const int p0 = blockIdx.x * 64;

    for (int i = tid; i < 64 * 128; i += 128) {
        int o = i >> 7, c = i & 127;
        wbf[o * 136 + c] = bfbits(fc2w[i]);
    }
    for (int i = tid; i < 128 * 32; i += 128) {
        int c = i >> 5, u = i & 31;
        *reinterpret_cast<uint*>(&actb[c * 72 + 2 * u]) =
            *reinterpret_cast<const uint*>(&g_h1b[c * NPIX + p0 + 2 * u]);
    }
    __syncthreads();

    const int wid = tid >> 5, lane = tid & 31;
    const int gid = lane >> 2, tig = lane & 3;
    const int q4 = lane >> 3, r4 = lane & 7;
    const int lr = lane & 15;
    const int m0 = wid * 16;

    uint a[8][4];
    #pragma unroll
    for (int ks = 0; ks < 8; ks++) {
        int arow = m0 + r4 + ((q4 & 1) << 3);
        int acol = ks * 16 + ((q4 >> 1) << 3);
        ldsm_x4(a[ks][0], a[ks][1], a[ks][2], a[ks][3], sptr(&wbf[arow * 136 + acol]));
    }
    float c[8][4];
    #pragma unroll
    for (int nt = 0; nt < 8; nt++)
        #pragma unroll
        for (int i = 0; i < 4; i++) c[nt][i] = 0.f;
    #pragma unroll
    for (int nt = 0; nt < 8; nt++) {
        #pragma unroll
        for (int ks = 0; ks < 8; ks++) {
            uint b0, b1;
            ldsm_x2t(b0, b1, sptr(&actb[(ks * 16 + lr) * 72 + nt * 8]));
            mma16816(c[nt], a[ks], b0, b1);
        }
    }

    // direct epilogue from acc regs
    const int ch0 = m0 + gid, ch1 = ch0 + 8;
    const float fb0 = fc2b[ch0], gg0 = g2[ch0];
    const float fb1 = fc2b[ch1], gg1 = g2[ch1];
    #pragma unroll
    for (int nt = 0; nt < 8; nt++) {
        int p = p0 + nt * 8 + 2 * tig;
        float2 x0 = *reinterpret_cast<const float2*>(&g_x1[ch0 * NPIX + p]);
        float2 x1 = *reinterpret_cast<const float2*>(&g_x1[ch1 * NPIX + p]);
        float2 o0 = make_float2(x0.x + gg0 * (c[nt][0] + fb0), x0.y + gg0 * (c[nt][1] + fb0));
        float2 o1 = make_float2(x1.x + gg1 * (c[nt][2] + fb1), x1.y + gg1 * (c[nt][3] + fb1));
        *reinterpret_cast<float2*>(&out[ch0 * NPIX + p]) = o0;
        *reinterpret_cast<float2*>(&out[ch1 * NPIX + p]) = o1;
    }
}

// =================================================================
extern "C" void kernel_launch(void* const* d_in, const int* in_sizes, int n_in,
                              void* d_out, int out_size)
{
    const float* x     = (const float*)d_in[0];
    const float* n1w   = (const float*)d_in[1];
    const float* n1b   = (const float*)d_in[2];
    const float* qkvw  = (const float*)d_in[3];
    const float* qkvb  = (const float*)d_in[4];
    const float* qnw   = (const float*)d_in[5];
    const float* qnb   = (const float*)d_in[6];
    const float* knw   = (const float*)d_in[7];
    const float* knb   = (const float*)d_in[8];
    const float* projw = (const float*)d_in[9];
    const float* projb = (const float*)d_in[10];
    const float* g1    = (const float*)d_in[11];
    const float* n2w   = (const float*)d_in[12];
    const float* n2b   = (const float*)d_in[13];
    const float* fc1w  = (const float*)d_in[14];
    const float* fc1b  = (const float*)d_in[15];
    const float* mnw   = (const float*)d_in[16];
    const float* mnb   = (const float*)d_in[17];
    const float* fc2w  = (const float*)d_in[18];
    const float* fc2b  = (const float*)d_in[19];
    const float* g2    = (const float*)d_in[20];
    float* out = (float*)d_out;

    cudaFuncSetAttribute(kA, cudaFuncAttributeMaxDynamicSharedMemorySize, SMEM_A);
    cudaFuncSetAttribute(kB, cudaFuncAttributeMaxDynamicSharedMemorySize, SMEM_B);
    cudaFuncSetAttribute(kC, cudaFuncAttributeMaxDynamicSharedMemorySize, SMEM_C);
    cudaFuncSetAttribute(kD, cudaFuncAttributeMaxDynamicSharedMemorySize, SMEM_D);
    cudaFuncSetAttribute(kE, cudaFuncAttributeMaxDynamicSharedMemorySize, SMEM_E);

    kA<<<256, 384, SMEM_A>>>(x, n1w, n1b, qkvw, qkvb, qnw, qnb, knw, knb);
    kB<<<dim3(32, 8), 128, SMEM_B>>>();
    kC<<<256, 128, SMEM_C>>>(x, projw, projb, g1, n2w, n2b);
    kD<<<256, 256, SMEM_D>>>(fc1w, fc1b, mnw, mnb);
    kE<<<256, 128, SMEM_E>>>(fc2w, fc2b, g2, out);
}

// round 8
// speedup vs baseline: 1.5960x; 1.1467x over previous
#include <cuda_runtime.h>
#include <cuda_bf16.h>

typedef unsigned long long ull;
typedef unsigned int uint;
typedef unsigned short ushort_t;

static constexpr int IMG   = 128;
static constexpr int NPIX  = IMG * IMG;      // 16384
static constexpr int CH    = 64;
static constexpr int NHEAD = 8;
static constexpr int HIDN  = 128;
static constexpr float LNEPS  = 1e-5f;
static constexpr float QSCALE = 0.35355339059327373f;   // 8^-0.5

// ---------------- scratch ----------------
__device__ __align__(16) float    g_q  [NHEAD * NPIX * 8];
__device__ __align__(16) ushort_t g_kb [NHEAD * NPIX * 8];
__device__ __align__(16) ushort_t g_vb [NHEAD * NPIX * 8];
__device__ __align__(16) ushort_t g_attb[CH * NPIX];
__device__ __align__(16) float    g_x1 [CH * NPIX];

// ---------------- helpers ----------------
#define FMA2(acc, a, b) asm("fma.rn.f32x2 %0, %1, %2, %0;" : "+l"(acc) : "l"(a), "l"(b))

__device__ __forceinline__ ull pk(float lo, float hi) {
    ull r; asm("mov.b64 %0, {%1, %2};" : "=l"(r) : "f"(lo), "f"(hi)); return r;
}
__device__ __forceinline__ float2 upk(ull v) {
    float2 r; asm("mov.b64 {%0, %1}, %2;" : "=f"(r.x), "=f"(r.y) : "l"(v)); return r;
}
__device__ __forceinline__ uint packbf(float a, float b) {
    __nv_bfloat162 h = __floats2bfloat162_rn(a, b);
    return *reinterpret_cast<uint*>(&h);
}
__device__ __forceinline__ ushort_t bfbits(float v) {
    __nv_bfloat16 b = __float2bfloat16_rn(v);
    return *reinterpret_cast<ushort_t*>(&b);
}
__device__ __forceinline__ ull b2u(uint u) {
    return pk(__uint_as_float(u << 16), __uint_as_float(u & 0xffff0000u));
}
__device__ __forceinline__ uint sptr(const void* p) {
    return (uint)__cvta_generic_to_shared(p);
}
__device__ __forceinline__ void ldsm_x4(uint &r0, uint &r1, uint &r2, uint &r3, uint addr) {
    asm volatile("ldmatrix.sync.aligned.m8n8.x4.shared.b16 {%0,%1,%2,%3}, [%4];"
                 : "=r"(r0), "=r"(r1), "=r"(r2), "=r"(r3) : "r"(addr));
}
__device__ __forceinline__ void ldsm_x2t(uint &r0, uint &r1, uint addr) {
    asm volatile("ldmatrix.sync.aligned.m8n8.x2.trans.shared.b16 {%0,%1}, [%2];"
                 : "=r"(r0), "=r"(r1) : "r"(addr));
}
__device__ __forceinline__ void mma16816(float* c, const uint* a, uint b0, uint b1) {
    asm volatile("mma.sync.aligned.m16n8k16.row.col.f32.bf16.bf16.f32 "
                 "{%0,%1,%2,%3}, {%4,%5,%6,%7}, {%8,%9}, {%0,%1,%2,%3};"
                 : "+f"(c[0]), "+f"(c[1]), "+f"(c[2]), "+f"(c[3])
                 : "r"(a[0]), "r"(a[1]), "r"(a[2]), "r"(a[3]), "r"(b0), "r"(b1));
}

// =================================================================
// Kernel A: LN1 -> QKV MMA GEMM -> qLN/kLN -> q fp32, k/v bf16
// (unchanged from R7)
// =================================================================
static constexpr int SMEM_A = 192 * 72 * 2 + 64 * 72 * 2;   // 36864

__global__ void __launch_bounds__(384, 2)
kA(const float* __restrict__ x, const float* __restrict__ n1w, const float* __restrict__ n1b,
   const float* __restrict__ qkvw, const float* __restrict__ qkvb,
   const float* __restrict__ qnw, const float* __restrict__ qnb,
   const float* __restrict__ knw, const float* __restrict__ knb)
{
    extern __shared__ float sm[];
    ushort_t* wbf  = reinterpret_cast<ushort_t*>(sm);          // [192][72]
    ushort_t* actb = wbf + 192 * 72;                           // [64][72]
    float*    stage = sm;                                      // [128][68] aliased
    const int tid = threadIdx.x;
    const int p0 = blockIdx.x * 64;

    for (int i = tid; i < 192 * 64; i += 384) {
        int o = i >> 6, c = i & 63;
        wbf[o * 72 + c] = bfbits(qkvw[i]);
    }
    if (tid < 256) {
        const int s = tid & 3, px = tid >> 2;
        const int p = p0 + px;
        float xv[16];
        float sum = 0.f, sq = 0.f;
        #pragma unroll
        for (int j = 0; j < 16; j++) {
            float v = x[(s * 16 + j) * NPIX + p];
            xv[j] = v; sum += v; sq += v * v;
        }
        sum += __shfl_xor_sync(0xffffffffu, sum, 1);
        sum += __shfl_xor_sync(0xffffffffu, sum, 2);
        sq  += __shfl_xor_sync(0xffffffffu, sq, 1);
        sq  += __shfl_xor_sync(0xffffffffu, sq, 2);
        float mean = sum * (1.f / 64);
        float inv = rsqrtf(sq * (1.f / 64) - mean * mean + LNEPS);
        #pragma unroll
        for (int j = 0; j < 16; j++) {
            int c = s * 16 + j;
            actb[c * 72 + px] = bfbits((xv[j] - mean) * inv * n1w[c] + n1b[c]);
        }
    }
    __syncthreads();

    const int wid = tid >> 5, lane = tid & 31;
    const int gid = lane >> 2, tig = lane & 3;
    const int q4 = lane >> 3, r4 = lane & 7;
    const int lr = lane & 15;
    const int m0 = wid * 16;

    uint a[4][4];
    #pragma unroll
    for (int ks = 0; ks < 4; ks++) {
        int arow = m0 + r4 + ((q4 & 1) << 3);
        int acol = ks * 16 + ((q4 >> 1) << 3);
        ldsm_x4(a[ks][0], a[ks][1], a[ks][2], a[ks][3], sptr(&wbf[arow * 72 + acol]));
    }
    float c[8][4];
    #pragma unroll
    for (int nt = 0; nt < 8; nt++)
        #pragma unroll
        for (int i = 0; i < 4; i++) c[nt][i] = 0.f;

    #pragma unroll
    for (int nt = 0; nt < 8; nt++) {
        #pragma unroll
        for (int ks = 0; ks < 4; ks++) {
            uint b0, b1;
            ldsm_x2t(b0, b1, sptr(&actb[(ks * 16 + lr) * 72 + nt * 8]));
            mma16816(c[nt], a[ks], b0, b1);
        }
    }
    __syncthreads();

    if (wid < 8) {
        #pragma unroll
        for (int nt = 0; nt < 8; nt++) {
            int col = nt * 8 + 2 * tig;
            *reinterpret_cast<float2*>(&stage[(m0 + gid) * 68 + col])     = make_float2(c[nt][0], c[nt][1]);
            *reinterpret_cast<float2*>(&stage[(m0 + 8 + gid) * 68 + col]) = make_float2(c[nt][2], c[nt][3]);
        }
    }
    __syncthreads();

    if (tid < 256) {
        const int s = tid & 3, px = tid >> 2;
        const int p = p0 + px;
        {
            float vv[16];
            float sum = 0.f, sq = 0.f;
            #pragma unroll
            for (int j = 0; j < 16; j++) {
                float v = stage[(s * 16 + j) * 68 + px] + qkvb[s * 16 + j];
                vv[j] = v; sum += v; sq += v * v;
            }
            sum += __shfl_xor_sync(0xffffffffu, sum, 1);
            sum += __shfl_xor_sync(0xffffffffu, sum, 2);
            sq  += __shfl_xor_sync(0xffffffffu, sq, 1);
            sq  += __shfl_xor_sync(0xffffffffu, sq, 2);
            float mean = sum * (1.f / 64);
            float inv = rsqrtf(sq * (1.f / 64) - mean * mean + LNEPS);
            #pragma unroll
            for (int j = 0; j < 16; j++) {
                int ch = s * 16 + j;
                vv[j] = ((vv[j] - mean) * inv * qnw[ch] + qnb[ch]) * QSCALE;
            }
            float4* d0 = reinterpret_cast<float4*>(&g_q[((2 * s) * NPIX + p) * 8]);
            d0[0] = make_float4(vv[0], vv[1], vv[2], vv[3]);
            d0[1] = make_float4(vv[4], vv[5], vv[6], vv[7]);
            float4* d1 = reinterpret_cast<float4*>(&g_q[((2 * s + 1) * NPIX + p) * 8]);
            d1[0] = make_float4(vv[8], vv[9], vv[10], vv[11]);
            d1[1] = make_float4(vv[12], vv[13], vv[14], vv[15]);
        }
        {
            float vv[16];
            float sum = 0.f, sq = 0.f;
            #pragma unroll
            for (int j = 0; j < 16; j++) {
                float v = stage[(64 + s * 16 + j) * 68 + px] + qkvb[64 + s * 16 + j];
                vv[j] = v; sum += v; sq += v * v;
            }
            sum += __shfl_xor_sync(0xffffffffu, sum, 1);
            sum += __shfl_xor_sync(0xffffffffu, sum, 2);
            sq  += __shfl_xor_sync(0xffffffffu, sq, 1);
            sq  += __shfl_xor_sync(0xffffffffu, sq, 2);
            float mean = sum * (1.f / 64);
            float inv = rsqrtf(sq * (1.f / 64) - mean * mean + LNEPS);
            #pragma unroll
            for (int j = 0; j < 16; j++) {
                int ch = s * 16 + j;
                vv[j] = (vv[j] - mean) * inv * knw[ch] + knb[ch];
            }
            uint4 u0, u1;
            u0.x = packbf(vv[0], vv[1]);  u0.y = packbf(vv[2], vv[3]);
            u0.z = packbf(vv[4], vv[5]);  u0.w = packbf(vv[6], vv[7]);
            u1.x = packbf(vv[8], vv[9]);  u1.y = packbf(vv[10], vv[11]);
            u1.z = packbf(vv[12], vv[13]); u1.w = packbf(vv[14], vv[15]);
            *reinterpret_cast<uint4*>(&g_kb[((2 * s) * NPIX + p) * 8])     = u0;
            *reinterpret_cast<uint4*>(&g_kb[((2 * s + 1) * NPIX + p) * 8]) = u1;
        }
    }
    __syncthreads();

    if (wid >= 8) {
        int mv0 = (wid - 8) * 16;
        #pragma unroll
        for (int nt = 0; nt < 8; nt++) {
            int col = nt * 8 + 2 * tig;
            *reinterpret_cast<float2*>(&stage[(mv0 + gid) * 68 + col])     = make_float2(c[nt][0], c[nt][1]);
            *reinterpret_cast<float2*>(&stage[(mv0 + 8 + gid) * 68 + col]) = make_float2(c[nt][2], c[nt][3]);
        }
    }
    __syncthreads();

    if (tid < 256) {
        const int s = tid & 3, px = tid >> 2;
        const int p = p0 + px;
        float vv[16];
        #pragma unroll
        for (int j = 0; j < 16; j++)
            vv[j] = stage[(s * 16 + j) * 68 + px] + qkvb[128 + s * 16 + j];
        uint4 u0, u1;
        u0.x = packbf(vv[0], vv[1]);  u0.y = packbf(vv[2], vv[3]);
        u0.z = packbf(vv[4], vv[5]);  u0.w = packbf(vv[6], vv[7]);
        u1.x = packbf(vv[8], vv[9]);  u1.y = packbf(vv[10], vv[11]);
        u1.z = packbf(vv[12], vv[13]); u1.w = packbf(vv[14], vv[15]);
        *reinterpret_cast<uint4*>(&g_vb[((2 * s) * NPIX + p) * 8])     = u0;
        *reinterpret_cast<uint4*>(&g_vb[((2 * s + 1) * NPIX + p) * 8]) = u1;
    }
}

// =================================================================
// Kernel B: neighborhood attention (unchanged from R7)
// =================================================================
static constexpr int HS_B = 67;
static constexpr int PL_B = 44 * HS_B;
static constexpr int SMEM_B = 2 * PL_B * 16;          // 94336 B

__device__ __forceinline__ int bswz(int c) { return c ^ (((c >> 4) & 1) << 2); }

__global__ void __launch_bounds__(128)
kB()
{
    extern __shared__ uint4 smu[];
    const int tile = blockIdx.x, head = blockIdx.y;
    const int th0 = (tile >> 2) * 16, tw0 = (tile & 3) * 32;
    const int tid = threadIdx.x;
    const ushort_t* kg = g_kb + head * (NPIX * 8);
    const ushort_t* vg = g_vb + head * (NPIX * 8);

    for (int e = tid; e < 2 * 44 * 60; e += 128) {
        int arr = (e >= 44 * 60) ? 1 : 0;
        int i = e - arr * (44 * 60);
        int r = i / 60, col = i - r * 60;
        int hh = min(max(th0 - 16 + r, 0), 127);
        int ww = min(max(tw0 - 16 + col, 0), 127);
        const ushort_t* src = arr ? vg : kg;
        smu[arr * PL_B + r * HS_B + bswz(col)] =
            *reinterpret_cast<const uint4*>(src + (hh * 128 + ww) * 8);
    }
    __syncthreads();

    const int qy   = tid >> 3;
    const int qx8  = tid & 7;
    const int wloc = (qx8 & 3) + ((qx8 >> 2) << 4);
    const int h  = th0 + qy;
    const int wb = tw0 + wloc;

    ulonglong2 qA[4], qB[4];
    #pragma unroll
    for (int t = 0; t < 4; t++) {
        const float* qp = &g_q[(head * NPIX + h * 128 + wb + 4 * t) * 8];
        qA[t] = *reinterpret_cast<const ulonglong2*>(qp);
        qB[t] = *reinterpret_cast<const ulonglong2*>(qp + 4);
    }

    float l[4] = {0.f, 0.f, 0.f, 0.f};
    ull acc2[4][4];
    #pragma unroll
    for (int t = 0; t < 4; t++)
        #pragma unroll
        for (int i = 0; i < 4; i++) acc2[t][i] = 0ull;

    #pragma unroll
    for (int a = 0; a < 8; a++) {
        int oh = 4 * a - 16;
        bool vr = (unsigned)(h + oh) < 128u;
        int rbase = (qy + 16 + oh) * HS_B;
        #pragma unroll
        for (int s = 0; s < 11; s++) {
            int off = rbase + bswz(wloc + 4 * s);
            bool ok = vr && ((unsigned)(wb + 4 * s - 16) < 128u);
            uint4 ku = smu[off];
            uint4 vu = smu[PL_B + off];
            ull kp0 = b2u(ku.x), kp1 = b2u(ku.y), kp2 = b2u(ku.z), kp3 = b2u(ku.w);
            ull vp0 = b2u(vu.x), vp1 = b2u(vu.y), vp2 = b2u(vu.z), vp3 = b2u(vu.w);
            #pragma unroll
            for (int t = 0; t < 4; t++) {
                if (t > s || t < s - 7) continue;
                ull s2 = 0ull;
                FMA2(s2, kp0, qA[t].x);
                FMA2(s2, kp1, qA[t].y);
                FMA2(s2, kp2, qB[t].x);
                FMA2(s2, kp3, qB[t].y);
                float2 sf = upk(s2);
                float sc = ok ? (sf.x + sf.y) : -1e30f;
                float ee = __expf(sc);
                l[t] += ee;
                ull e2 = pk(ee, ee);
                FMA2(acc2[t][0], vp0, e2);
                FMA2(acc2[t][1], vp1, e2);
                FMA2(acc2[t][2], vp2, e2);
                FMA2(acc2[t][3], vp3, e2);
            }
        }
    }
    #pragma unroll
    for (int t = 0; t < 4; t++) {
        float rl = 1.0f / l[t];
        int p = h * 128 + wb + 4 * t;
        #pragma unroll
        for (int i = 0; i < 4; i++) {
            float2 f = upk(acc2[t][i]);
            g_attb[(head * 8 + 2 * i)     * NPIX + p] = bfbits(f.x * rl);
            g_attb[(head * 8 + 2 * i + 1) * NPIX + p] = bfbits(f.y * rl);
        }
    }
}

// =================================================================
// Kernel CDE: proj+LN2 -> fc1+LN+SiLU -> fc2+residual, fully fused.
// 256 thr (8 warps), 64-px tiles, grid 256.  96KB smem, 2 blocks/SM.
// =================================================================
static constexpr int OFF_W1  = 0;                 // bf16 [64][72]   9216 B
static constexpr int OFF_W2  = 9216;              // bf16 [128][72] 18432 B
static constexpr int OFF_W3  = 27648;             // bf16 [64][136] 17408 B
static constexpr int OFF_ACT = 45056;             // bf16 [128][72] 18432 B
static constexpr int OFF_STG = 63488;             // fp32 [128][68] 34816 B
static constexpr int SMEM_F  = 98304;             // 96 KB

__global__ void __launch_bounds__(256, 2)
kCDE(const float* __restrict__ x,
     const float* __restrict__ projw, const float* __restrict__ projb,
     const float* __restrict__ g1, const float* __restrict__ n2w, const float* __restrict__ n2b,
     const float* __restrict__ fc1w, const float* __restrict__ fc1b,
     const float* __restrict__ mnw, const float* __restrict__ mnb,
     const float* __restrict__ fc2w, const float* __restrict__ fc2b,
     const float* __restrict__ g2, float* __restrict__ out)
{
    extern __shared__ char smc[];
    ushort_t* w1  = reinterpret_cast<ushort_t*>(smc + OFF_W1);
    ushort_t* w2  = reinterpret_cast<ushort_t*>(smc + OFF_W2);
    ushort_t* w3  = reinterpret_cast<ushort_t*>(smc + OFF_W3);
    ushort_t* act = reinterpret_cast<ushort_t*>(smc + OFF_ACT);
    float*    stg = reinterpret_cast<float*>(smc + OFF_STG);
    const int tid = threadIdx.x;
    const int p0 = blockIdx.x * 64;

    // ---- stage all weights (once) + att ----
    for (int i = tid; i < 64 * 64; i += 256) {
        int o = i >> 6, c = i & 63;
        w1[o * 72 + c] = bfbits(projw[i]);
    }
    for (int i = tid; i < 128 * 64; i += 256) {
        int o = i >> 6, c = i & 63;
        w2[o * 72 + c] = bfbits(fc1w[i]);
    }
    for (int i = tid; i < 64 * 128; i += 256) {
        int o = i >> 7, c = i & 127;
        w3[o * 136 + c] = bfbits(fc2w[i]);
    }
    for (int i = tid; i < 64 * 32; i += 256) {
        int c = i >> 5, u = i & 31;
        *reinterpret_cast<uint*>(&act[c * 72 + 2 * u]) =
            *reinterpret_cast<const uint*>(&g_attb[c * NPIX + p0 + 2 * u]);
    }
    __syncthreads();

    const int wid = tid >> 5, lane = tid & 31;
    const int gid = lane >> 2, tig = lane & 3;
    const int q4 = lane >> 3, r4 = lane & 7;
    const int lr = lane & 15;

    // ================= GEMM1: proj (64 outs, split N across warp pairs) ====
    {
        const int ot = wid & 3, nh = wid >> 2;
        const int m0 = ot * 16;
        uint a[4][4];
        #pragma unroll
        for (int ks = 0; ks < 4; ks++) {
            int arow = m0 + r4 + ((q4 & 1) << 3);
            int acol = ks * 16 + ((q4 >> 1) << 3);
            ldsm_x4(a[ks][0], a[ks][1], a[ks][2], a[ks][3], sptr(&w1[arow * 72 + acol]));
        }
        float c[4][4];
        #pragma unroll
        for (int nt = 0; nt < 4; nt++)
            #pragma unroll
            for (int i = 0; i < 4; i++) c[nt][i] = 0.f;
        #pragma unroll
        for (int nt = 0; nt < 4; nt++) {
            int ntg = nh * 4 + nt;
            #pragma unroll
            for (int ks = 0; ks < 4; ks++) {
                uint b0, b1;
                ldsm_x2t(b0, b1, sptr(&act[(ks * 16 + lr) * 72 + ntg * 8]));
                mma16816(c[nt], a[ks], b0, b1);
            }
        }
        __syncthreads();
        #pragma unroll
        for (int nt = 0; nt < 4; nt++) {
            int col = (nh * 4 + nt) * 8 + 2 * tig;
            *reinterpret_cast<float2*>(&stg[(m0 + gid) * 68 + col])     = make_float2(c[nt][0], c[nt][1]);
            *reinterpret_cast<float2*>(&stg[(m0 + 8 + gid) * 68 + col]) = make_float2(c[nt][2], c[nt][3]);
        }
        __syncthreads();
    }

    // ============ Epilogue1: x1 = x + g1*(o+pb); LN2 -> y (act) ============
    {
        const int s = tid & 3, px = tid >> 2;
        const int p = p0 + px;
        float vv[16];
        float sum = 0.f, sq = 0.f;
        #pragma unroll
        for (int j = 0; j < 16; j++) {
            int ch = s * 16 + j;
            float v = x[ch * NPIX + p] + g1[ch] * (stg[ch * 68 + px] + projb[ch]);
            g_x1[ch * NPIX + p] = v;
            vv[j] = v; sum += v; sq += v * v;
        }
        sum += __shfl_xor_sync(0xffffffffu, sum, 1);
        sum += __shfl_xor_sync(0xffffffffu, sum, 2);
        sq  += __shfl_xor_sync(0xffffffffu, sq, 1);
        sq  += __shfl_xor_sync(0xffffffffu, sq, 2);
        float mean = sum * (1.f / 64);
        float inv = rsqrtf(sq * (1.f / 64) - mean * mean + LNEPS);
        #pragma unroll
        for (int j = 0; j < 16; j++) {
            int ch = s * 16 + j;
            act[ch * 72 + px] = bfbits((vv[j] - mean) * inv * n2w[ch] + n2b[ch]);
        }
        __syncthreads();
    }

    // ================= GEMM2: fc1 (128 outs, 8 warp tiles) =================
    {
        const int m0 = wid * 16;
        uint a[4][4];
        #pragma unroll
        for (int ks = 0; ks < 4; ks++) {
            int arow = m0 + r4 + ((q4 & 1) << 3);
            int acol = ks * 16 + ((q4 >> 1) << 3);
            ldsm_x4(a[ks][0], a[ks][1], a[ks][2], a[ks][3], sptr(&w2[arow * 72 + acol]));
        }
        float c[8][4];
        #pragma unroll
        for (int nt = 0; nt < 8; nt++)
            #pragma unroll
            for (int i = 0; i < 4; i++) c[nt][i] = 0.f;
        #pragma unroll
        for (int nt = 0; nt < 8; nt++) {
            #pragma unroll
            for (int ks = 0; ks < 4; ks++) {
                uint b0, b1;
                ldsm_x2t(b0, b1, sptr(&act[(ks * 16 + lr) * 72 + nt * 8]));
                mma16816(c[nt], a[ks], b0, b1);
            }
        }
        __syncthreads();
        #pragma unroll
        for (int nt = 0; nt < 8; nt++) {
            int col = nt * 8 + 2 * tig;
            *reinterpret_cast<float2*>(&stg[(m0 + gid) * 68 + col])     = make_float2(c[nt][0], c[nt][1]);
            *reinterpret_cast<float2*>(&stg[(m0 + 8 + gid) * 68 + col]) = make_float2(c[nt][2], c[nt][3]);
        }
        __syncthreads();
    }

    // ============ Epilogue2: LN(128) + SiLU -> h1 (act rows 0-127) =========
    {
        const int s = tid & 3, px = tid >> 2;
        float vv[32];
        float sum = 0.f, sq = 0.f;
        #pragma unroll
        for (int j = 0; j < 32; j++) {
            int ch = s * 32 + j;
            float v = stg[ch * 68 + px] + fc1b[ch];
            vv[j] = v; sum += v; sq += v * v;
        }
        sum += __shfl_xor_sync(0xffffffffu, sum, 1);
        sum += __shfl_xor_sync(0xffffffffu, sum, 2);
        sq  += __shfl_xor_sync(0xffffffffu, sq, 1);
        sq  += __shfl_xor_sync(0xffffffffu, sq, 2);
        float mean = sum * (1.f / 128);
        float inv = rsqrtf(sq * (1.f / 128) - mean * mean + LNEPS);
        #pragma unroll
        for (int j = 0; j < 32; j++) {
            int ch = s * 32 + j;
            float hh = (vv[j] - mean) * inv * mnw[ch] + mnb[ch];
            act[ch * 72 + px] = bfbits(hh / (1.f + __expf(-hh)));
        }
        __syncthreads();
    }

    // ======== GEMM3: fc2 (64 outs, split N) + direct residual epilogue =====
    {
        const int ot = wid & 3, nh = wid >> 2;
        const int m0 = ot * 16;
        uint a[8][4];
        #pragma unroll
        for (int ks = 0; ks < 8; ks++) {
            int arow = m0 + r4 + ((q4 & 1) << 3);
            int acol = ks * 16 + ((q4 >> 1) << 3);
            ldsm_x4(a[ks][0], a[ks][1], a[ks][2], a[ks][3], sptr(&w3[arow * 136 + acol]));
        }
        float c[4][4];
        #pragma unroll
        for (int nt = 0; nt < 4; nt++)
            #pragma unroll
            for (int i = 0; i < 4; i++) c[nt][i] = 0.f;
        #pragma unroll
        for (int nt = 0; nt < 4; nt++) {
            int ntg = nh * 4 + nt;
            #pragma unroll
            for (int ks = 0; ks < 8; ks++) {
                uint b0, b1;
                ldsm_x2t(b0, b1, sptr(&act[(ks * 16 + lr) * 72 + ntg * 8]));
                mma16816(c[nt], a[ks], b0, b1);
            }
        }
        const int ch0 = m0 + gid, ch1 = ch0 + 8;
        const float fb0 = fc2b[ch0], gg0 = g2[ch0];
        const float fb1 = fc2b[ch1], gg1 = g2[ch1];
        #pragma unroll
        for (int nt = 0; nt < 4; nt++) {
            int p = p0 + (nh * 4 + nt) * 8 + 2 * tig;
            float2 x0 = *reinterpret_cast<const float2*>(&g_x1[ch0 * NPIX + p]);
            float2 x1 = *reinterpret_cast<const float2*>(&g_x1[ch1 * NPIX + p]);
            float2 o0 = make_float2(x0.x + gg0 * (c[nt][0] + fb0), x0.y + gg0 * (c[nt][1] + fb0));
            float2 o1 = make_float2(x1.x + gg1 * (c[nt][2] + fb1), x1.y + gg1 * (c[nt][3] + fb1));
            *reinterpret_cast<float2*>(&out[ch0 * NPIX + p]) = o0;
            *reinterpret_cast<float2*>(&out[ch1 * NPIX + p]) = o1;
        }
    }
}

// =================================================================
extern "C" void kernel_launch(void* const* d_in, const int* in_sizes, int n_in,
                              void* d_out, int out_size)
{
    const float* x     = (const float*)d_in[0];
    const float* n1w   = (const float*)d_in[1];
    const float* n1b   = (const float*)d_in[2];
    const float* qkvw  = (const float*)d_in[3];
    const float* qkvb  = (const float*)d_in[4];
    const float* qnw   = (const float*)d_in[5];
    const float* qnb   = (const float*)d_in[6];
    const float* knw   = (const float*)d_in[7];
    const float* knb   = (const float*)d_in[8];
    const float* projw = (const float*)d_in[9];
    const float* projb = (const float*)d_in[10];
    const float* g1    = (const float*)d_in[11];
    const float* n2w   = (const float*)d_in[12];
    const float* n2b   = (const float*)d_in[13];
    const float* fc1w  = (const float*)d_in[14];
    const float* fc1b  = (const float*)d_in[15];
    const float* mnw   = (const float*)d_in[16];
    const float* mnb   = (const float*)d_in[17];
    const float* fc2w  = (const float*)d_in[18];
    const float* fc2b  = (const float*)d_in[19];
    const float* g2    = (const float*)d_in[20];
    float* out = (float*)d_out;

    cudaFuncSetAttribute(kA,   cudaFuncAttributeMaxDynamicSharedMemorySize, SMEM_A);
    cudaFuncSetAttribute(kB,   cudaFuncAttributeMaxDynamicSharedMemorySize, SMEM_B);
    cudaFuncSetAttribute(kCDE, cudaFuncAttributeMaxDynamicSharedMemorySize, SMEM_F);

    kA<<<256, 384, SMEM_A>>>(x, n1w, n1b, qkvw, qkvb, qnw, qnb, knw, knb);
    kB<<<dim3(32, 8), 128, SMEM_B>>>();
    kCDE<<<256, 256, SMEM_F>>>(x, projw, projb, g1, n2w, n2b,
                               fc1w, fc1b, mnw, mnb, fc2w, fc2b, g2, out);
}